// round 2
// baseline (speedup 1.0000x reference)
#include <cuda_runtime.h>
#include <cuda_bf16.h>
#include <math.h>

// Problem constants (fixed shapes from reference)
#define QN    16
#define C0N   8
#define C1N   4
#define DIMC  20
#define K3T   125
#define NCH   320
#define VOX   512
#define GK    8
#define NSPLIT 20

__device__ float g_kern[NCH * NCH * K3T];     // [ci][och][tap]
__device__ float g_part[NSPLIT * NCH * VOX];  // [split][och][vox]

// ---------------------------------------------------------------------------
// Kernel 1: build the equivariant conv kernel.
// blockIdx.y selects CG path (0=ss, 1=sv, 2=vs, 3=vv) for 4x parallelism.
// ---------------------------------------------------------------------------
__global__ void build_kern_kernel(const float* __restrict__ q_in,
                                  const float* __restrict__ q_out,
                                  const float* __restrict__ w_ss,
                                  const float* __restrict__ w_vs,
                                  const float* __restrict__ w_sv,
                                  const float* __restrict__ w_vv0,
                                  const float* __restrict__ w_vv1) {
    int idx = blockIdx.x * blockDim.x + threadIdx.x;
    if (idx >= QN * QN * K3T) return;
    int t = idx % K3T;
    int q = (idx / K3T) % QN;
    int p = idx / (K3T * QN);
    int path = blockIdx.y;

    int dz = t / 25, dy = (t / 5) % 5, dx = t % 5;
    float v0 = (float)(dz - 2) - (q_out[p * 3 + 0] - q_in[q * 3 + 0]);
    float v1 = (float)(dy - 2) - (q_out[p * 3 + 1] - q_in[q * 3 + 1]);
    float v2 = (float)(dx - 2) - (q_out[p * 3 + 2] - q_in[q * 3 + 2]);
    float r  = sqrtf(v0 * v0 + v1 * v1 + v2 * v2);
    float inv = (r > 1e-6f) ? (1.0f / r) : 0.0f;
    float u[3] = {v0 * inv, v1 * inv, v2 * inv};

    const float sigma = 5.5f / 7.0f;
    float R[GK];
#pragma unroll
    for (int g = 0; g < GK; g++) {
        float d = (r - sigma * (float)g) / sigma;
        R[g] = expf(-0.5f * d * d);
    }

    float cross[3][3];
    cross[0][0] = 0.f;    cross[0][1] = -u[2];  cross[0][2] =  u[1];
    cross[1][0] =  u[2];  cross[1][1] = 0.f;    cross[1][2] = -u[0];
    cross[2][0] = -u[1];  cross[2][1] =  u[0];  cross[2][2] = 0.f;

#define KSTORE(row, col, val) \
    g_kern[((size_t)(((col) * QN + q)) * NCH + ((row) * QN + p)) * K3T + t] = (val)

    if (path == 0) {                       // scalar->scalar
        for (int a = 0; a < C0N; a++)
            for (int c = 0; c < C0N; c++) {
                float s = 0.f;
#pragma unroll
                for (int g = 0; g < GK; g++) s += w_ss[(a * C0N + c) * GK + g] * R[g];
                KSTORE(a, c, s);
            }
    } else if (path == 1) {                // vector-in -> scalar-out
        for (int a = 0; a < C0N; a++)
            for (int c = 0; c < C1N; c++) {
                float s = 0.f;
#pragma unroll
                for (int g = 0; g < GK; g++) s += w_sv[(a * C1N + c) * GK + g] * R[g];
#pragma unroll
                for (int j = 0; j < 3; j++) KSTORE(a, 8 + c * 3 + j, s * u[j]);
            }
    } else if (path == 2) {                // scalar-in -> vector-out
        for (int a = 0; a < C1N; a++)
            for (int c = 0; c < C0N; c++) {
                float s = 0.f;
#pragma unroll
                for (int g = 0; g < GK; g++) s += w_vs[(a * C0N + c) * GK + g] * R[g];
#pragma unroll
                for (int m = 0; m < 3; m++) KSTORE(8 + a * 3 + m, c, s * u[m]);
            }
    } else {                               // vector->vector (id + cross)
        for (int a = 0; a < C1N; a++)
            for (int c = 0; c < C1N; c++) {
                float d0 = 0.f, d1 = 0.f;
#pragma unroll
                for (int g = 0; g < GK; g++) {
                    d0 += w_vv0[(a * C1N + c) * GK + g] * R[g];
                    d1 += w_vv1[(a * C1N + c) * GK + g] * R[g];
                }
#pragma unroll
                for (int i = 0; i < 3; i++)
#pragma unroll
                    for (int j = 0; j < 3; j++) {
                        float val = ((i == j) ? d0 : 0.f)
                                  + 0.7071067811865476f * d1 * cross[i][j];
                        KSTORE(8 + a * 3 + i, 8 + c * 3 + j, val);
                    }
            }
    }
#undef KSTORE
}

// ---------------------------------------------------------------------------
// Kernel 2: split-K implicit GEMM, fp32 via packed fma.rn.f32x2 (FFMA2).
// Thread tile: 8 och x 8 vox = 8 och x 4 f32x2-pairs.
// Kern values pre-duplicated (k,k) in smem -> one broadcast LDS.64 per och.
// ---------------------------------------------------------------------------
#define SY 13
#define SZ 168

__global__ void __launch_bounds__(256, 2)
gemm_kernel(const float* __restrict__ x) {
    __shared__ float  xp[12 * SZ];         // padded 12x12x12 (~8KB)
    __shared__ float2 ks2[K3T * 32];       // kern tile, duplicated halves (32KB)

    const int tid   = threadIdx.x;
    const int och0  = blockIdx.x * 32;
    const int ksp   = blockIdx.y;
    const int o_sub = tid >> 6;            // 0..3
    const int v_sub = tid & 63;            // (z,y) row
    const int z = v_sub >> 3, y = v_sub & 7;

    unsigned long long acc2[8][4];
#pragma unroll
    for (int o = 0; o < 8; o++)
#pragma unroll
        for (int i = 0; i < 4; i++) acc2[o][i] = 0ULL;

    for (int i = tid; i < 12 * SZ; i += 256) xp[i] = 0.f;

    for (int ci_it = 0; ci_it < 16; ++ci_it) {
        const int ci = ksp * 16 + ci_it;
        __syncthreads();
        for (int i = tid; i < VOX; i += 256) {
            int zz = i >> 6, yy = (i >> 3) & 7, xx = i & 7;
            xp[(zz + 2) * SZ + (yy + 2) * SY + (xx + 2)] = x[ci * VOX + i];
        }
        for (int i = tid; i < 32 * K3T; i += 256) {
            int o = i / K3T, t = i - o * K3T;
            float v = g_kern[((size_t)ci * NCH + (och0 + o)) * K3T + t];
            ks2[t * 32 + o] = make_float2(v, v);
        }
        __syncthreads();

        const int base0 = z * SZ + y * SY;
        for (int dz5 = 0; dz5 < 5; dz5++) {
            for (int dy5 = 0; dy5 < 5; dy5++) {
                const float* xrow = &xp[base0 + dz5 * SZ + dy5 * SY];
                const unsigned long long* kp0 =
                    (const unsigned long long*)(ks2 + ((dz5 * 5 + dy5) * 5) * 32 + o_sub * 8);
#pragma unroll
                for (int dx5 = 0; dx5 < 5; dx5++) {
                    float xv[8];
#pragma unroll
                    for (int i = 0; i < 8; i++) xv[i] = xrow[dx5 + i];
                    unsigned long long xvp[4];
#pragma unroll
                    for (int i = 0; i < 4; i++)
                        asm("mov.b64 %0, {%1, %2};"
                            : "=l"(xvp[i]) : "f"(xv[2 * i]), "f"(xv[2 * i + 1]));
                    const unsigned long long* kp = kp0 + dx5 * 32;
#pragma unroll
                    for (int o = 0; o < 8; o++) {
                        unsigned long long kvp = kp[o];   // broadcast LDS.64 (k,k)
#pragma unroll
                        for (int i = 0; i < 4; i++)
                            asm("fma.rn.f32x2 %0, %1, %2, %0;"
                                : "+l"(acc2[o][i]) : "l"(kvp), "l"(xvp[i]));
                    }
                }
            }
        }
    }

    const int vbase = v_sub << 3;
#pragma unroll
    for (int o = 0; o < 8; o++) {
        int och = och0 + o_sub * 8 + o;
        float* dst = &g_part[((size_t)ksp * NCH + och) * VOX + vbase];
#pragma unroll
        for (int i = 0; i < 4; i++) {
            float lo, hi;
            asm("mov.b64 {%0, %1}, %2;" : "=f"(lo), "=f"(hi) : "l"(acc2[o][i]));
            dst[2 * i]     = lo;
            dst[2 * i + 1] = hi;
        }
    }
}

// ---------------------------------------------------------------------------
// Kernel 3: reduce split-K partials + bias.
// ---------------------------------------------------------------------------
__global__ void reduce_kernel(float* __restrict__ out,
                              const float* __restrict__ bias) {
    int i = blockIdx.x * blockDim.x + threadIdx.x;
    if (i >= NCH * VOX) return;
    int och = i >> 9;
    int r   = och >> 4;
    float s = (r < C0N) ? bias[r] : 0.f;
#pragma unroll
    for (int k = 0; k < NSPLIT; k++) s += g_part[(size_t)k * NCH * VOX + i];
    out[i] = s;
}

// ---------------------------------------------------------------------------
extern "C" void kernel_launch(void* const* d_in, const int* in_sizes, int n_in,
                              void* d_out, int out_size) {
    const float* x     = (const float*)d_in[0];
    const float* q_in  = (const float*)d_in[1];
    const float* q_out = (const float*)d_in[2];
    const float* w_ss  = (const float*)d_in[3];
    const float* w_vs  = (const float*)d_in[4];
    const float* w_sv  = (const float*)d_in[5];
    const float* w_vv0 = (const float*)d_in[6];
    const float* w_vv1 = (const float*)d_in[7];
    const float* bias  = (const float*)d_in[8];
    float* out = (float*)d_out;

    dim3 bgrid((QN * QN * K3T + 255) / 256, 4);
    build_kern_kernel<<<bgrid, 256>>>(q_in, q_out, w_ss, w_vs, w_sv, w_vv0, w_vv1);

    dim3 grid(NCH / 32, NSPLIT);
    gemm_kernel<<<grid, 256>>>(x);

    reduce_kernel<<<(NCH * VOX + 255) / 256, 256>>>(out, bias);
}

// round 4
// speedup vs baseline: 1.1321x; 1.1321x over previous
#include <cuda_runtime.h>
#include <cuda_bf16.h>
#include <math.h>
#include <stdint.h>

// ---------------- problem constants ----------------
#define QN    16
#define C0N   8
#define C1N   4
#define K3T   125
#define NCH   320
#define VOX   512
#define GK    8
#define NSPL  24
#define NCHUNK 625          // 125 taps * 5 ci-blocks of 64

// smem stage layout (bytes)
#define SOFF_AHI 0
#define SOFF_ALO 16384
#define SOFF_BHI 32768
#define SOFF_BLO 65536
#define STAGE_BYTES 98304
#define SMEM_TOTAL (2 * STAGE_BYTES)

// ---------------- device globals ----------------
__device__ __nv_bfloat16 gA_hi[(size_t)K3T * NCH * NCH];   // [tap][och][ci]
__device__ __nv_bfloat16 gA_lo[(size_t)K3T * NCH * NCH];
__device__ __nv_bfloat16 gXp_hi[1728 * NCH];               // [pz*144+py*12+px][ci]
__device__ __nv_bfloat16 gXp_lo[1728 * NCH];
__device__ float g_part[(size_t)NSPL * 6 * 128 * 256];     // [s][mt*2+nt][128][256]

// ---------------- helpers ----------------
__device__ __forceinline__ uint32_t smem_u32(const void* p) {
    uint32_t a;
    asm("{ .reg .u64 t; cvta.to.shared.u64 t, %1; cvt.u32.u64 %0, t; }" : "=r"(a) : "l"(p));
    return a;
}
#define SWZ(o) ((o) ^ (((o) >> 3) & 0x70))

__device__ __forceinline__ void cp16(uint32_t dst, const void* src, uint32_t nbytes) {
    asm volatile("cp.async.cg.shared.global [%0], [%1], 16, %2;"
                 :: "r"(dst), "l"(src), "r"(nbytes) : "memory");
}
__device__ __forceinline__ void cp_commit() { asm volatile("cp.async.commit_group;" ::: "memory"); }
__device__ __forceinline__ void cp_wait1()  { asm volatile("cp.async.wait_group 1;" ::: "memory"); }
__device__ __forceinline__ void cp_wait0()  { asm volatile("cp.async.wait_group 0;" ::: "memory"); }

__device__ __forceinline__ void ldm4(uint32_t& r0, uint32_t& r1, uint32_t& r2,
                                     uint32_t& r3, uint32_t addr) {
    asm volatile("ldmatrix.sync.aligned.m8n8.x4.shared.b16 {%0,%1,%2,%3}, [%4];"
                 : "=r"(r0), "=r"(r1), "=r"(r2), "=r"(r3) : "r"(addr));
}
__device__ __forceinline__ void mma16816(float* c, uint32_t a0, uint32_t a1,
                                         uint32_t a2, uint32_t a3,
                                         uint32_t b0, uint32_t b1) {
    asm volatile("mma.sync.aligned.m16n8k16.row.col.f32.bf16.bf16.f32 "
                 "{%0,%1,%2,%3}, {%4,%5,%6,%7}, {%8,%9}, {%0,%1,%2,%3};"
                 : "+f"(c[0]), "+f"(c[1]), "+f"(c[2]), "+f"(c[3])
                 : "r"(a0), "r"(a1), "r"(a2), "r"(a3), "r"(b0), "r"(b1));
}

// ---------------------------------------------------------------------------
// Kernel 1: x -> transposed + halo-padded bf16 hi/lo [1728 pos][320 ci]
// ---------------------------------------------------------------------------
__global__ void xpad_kernel(const float* __restrict__ x) {
    int i = blockIdx.x * blockDim.x + threadIdx.x;
    if (i >= 1728 * NCH) return;
    int ci = i % NCH, ppos = i / NCH;
    int px = ppos % 12, py = (ppos / 12) % 12, pz = ppos / 144;
    int z = pz - 2, y = py - 2, xx = px - 2;
    float v = 0.f;
    if ((unsigned)z < 8 && (unsigned)y < 8 && (unsigned)xx < 8)
        v = x[ci * VOX + z * 64 + y * 8 + xx];
    __nv_bfloat16 h = __float2bfloat16(v);
    gXp_hi[i] = h;
    gXp_lo[i] = __float2bfloat16(v - __bfloat162float(h));
}

// ---------------------------------------------------------------------------
// Kernel 2: build equivariant kernel -> gA_hi/gA_lo [tap][och][ci] bf16 split.
// ---------------------------------------------------------------------------
__global__ void build_kern_kernel(const float* __restrict__ q_in,
                                  const float* __restrict__ q_out,
                                  const float* __restrict__ w_ss,
                                  const float* __restrict__ w_vs,
                                  const float* __restrict__ w_sv,
                                  const float* __restrict__ w_vv0,
                                  const float* __restrict__ w_vv1) {
    int idx = blockIdx.x * blockDim.x + threadIdx.x;
    if (idx >= QN * QN * K3T) return;
    int t = idx % K3T;
    int q = (idx / K3T) % QN;
    int p = idx / (K3T * QN);
    int path = blockIdx.y;

    int dz = t / 25, dy = (t / 5) % 5, dx = t % 5;
    float v0 = (float)(dz - 2) - (q_out[p * 3 + 0] - q_in[q * 3 + 0]);
    float v1 = (float)(dy - 2) - (q_out[p * 3 + 1] - q_in[q * 3 + 1]);
    float v2 = (float)(dx - 2) - (q_out[p * 3 + 2] - q_in[q * 3 + 2]);
    float r  = sqrtf(v0 * v0 + v1 * v1 + v2 * v2);
    float inv = (r > 1e-6f) ? (1.0f / r) : 0.0f;
    float u[3] = {v0 * inv, v1 * inv, v2 * inv};

    const float sigma = 5.5f / 7.0f;
    float R[GK];
#pragma unroll
    for (int g = 0; g < GK; g++) {
        float d = (r - sigma * (float)g) / sigma;
        R[g] = expf(-0.5f * d * d);
    }

    float cross[3][3];
    cross[0][0] = 0.f;    cross[0][1] = -u[2];  cross[0][2] =  u[1];
    cross[1][0] =  u[2];  cross[1][1] = 0.f;    cross[1][2] = -u[0];
    cross[2][0] = -u[1];  cross[2][1] =  u[0];  cross[2][2] = 0.f;

#define KSTORE(row, col, val) do {                                         \
    float _v = (val);                                                      \
    __nv_bfloat16 _h = __float2bfloat16(_v);                               \
    __nv_bfloat16 _l = __float2bfloat16(_v - __bfloat162float(_h));        \
    size_t _o = ((size_t)t * NCH + ((row) * QN + p)) * NCH + ((col) * QN + q); \
    gA_hi[_o] = _h; gA_lo[_o] = _l; } while (0)

    if (path == 0) {
        for (int a = 0; a < C0N; a++)
            for (int c = 0; c < C0N; c++) {
                float s = 0.f;
#pragma unroll
                for (int g = 0; g < GK; g++) s += w_ss[(a * C0N + c) * GK + g] * R[g];
                KSTORE(a, c, s);
            }
    } else if (path == 1) {
        for (int a = 0; a < C0N; a++)
            for (int c = 0; c < C1N; c++) {
                float s = 0.f;
#pragma unroll
                for (int g = 0; g < GK; g++) s += w_sv[(a * C1N + c) * GK + g] * R[g];
#pragma unroll
                for (int j = 0; j < 3; j++) KSTORE(a, 8 + c * 3 + j, s * u[j]);
            }
    } else if (path == 2) {
        for (int a = 0; a < C1N; a++)
            for (int c = 0; c < C0N; c++) {
                float s = 0.f;
#pragma unroll
                for (int g = 0; g < GK; g++) s += w_vs[(a * C0N + c) * GK + g] * R[g];
#pragma unroll
                for (int m = 0; m < 3; m++) KSTORE(8 + a * 3 + m, c, s * u[m]);
            }
    } else {
        for (int a = 0; a < C1N; a++)
            for (int c = 0; c < C1N; c++) {
                float d0 = 0.f, d1 = 0.f;
#pragma unroll
                for (int g = 0; g < GK; g++) {
                    d0 += w_vv0[(a * C1N + c) * GK + g] * R[g];
                    d1 += w_vv1[(a * C1N + c) * GK + g] * R[g];
                }
#pragma unroll
                for (int i = 0; i < 3; i++)
#pragma unroll
                    for (int j = 0; j < 3; j++) {
                        float val = ((i == j) ? d0 : 0.f)
                                  + 0.7071067811865476f * d1 * cross[i][j];
                        KSTORE(8 + a * 3 + i, 8 + c * 3 + j, val);
                    }
            }
    }
#undef KSTORE
}

// ---------------------------------------------------------------------------
// Kernel 3: bf16 mma.sync split-K implicit GEMM.
// grid = (6 = 3 M-tiles x 2 N-tiles, NSPL), block = 512 (16 warps, 4Mx4N).
// Block tile M128 x N256; warp tile 32x64; 3 precision passes per chunk.
// ---------------------------------------------------------------------------
__device__ __forceinline__ void load_chunk(int c, uint32_t sbase, int tid,
                                           int och0, int z0) {
    int t   = c / 5;
    int ci0 = (c - t * 5) * 64;
    int dz = t / 25, r2 = t - dz * 25;
    int dy = r2 / 5, dx = r2 - dy * 5;

    const char* ahp = (const char*)gA_hi;
    const char* alp = (const char*)gA_lo;
    const char* bhp = (const char*)gXp_hi;
    const char* blp = (const char*)gXp_lo;

    // A tiles: 128 rows x 8 x 16B (hi+lo)
    for (int i = tid; i < 1024; i += 512) {
        int row = i >> 3, c16 = i & 7;
        int och = och0 + row;
        uint32_t ok = (och < NCH) ? 16u : 0u;
        size_t goff = (((size_t)t * NCH + (och < NCH ? och : 0)) * NCH + ci0 + c16 * 8) * 2;
        uint32_t sw = SWZ((uint32_t)(row * 128 + c16 * 16));
        cp16(sbase + SOFF_AHI + sw, ahp + goff, ok);
        cp16(sbase + SOFF_ALO + sw, alp + goff, ok);
    }
    // B tiles: 256 rows x 8 x 16B (hi+lo)
    for (int i = tid; i < 2048; i += 512) {
        int row = i >> 3, c16 = i & 7;
        int pz = z0 + (row >> 6) + dz;
        int py = ((row >> 3) & 7) + dy;
        int px = (row & 7) + dx;
        size_t goff = ((size_t)(pz * 144 + py * 12 + px) * NCH + ci0 + c16 * 8) * 2;
        uint32_t sw = SWZ((uint32_t)(row * 128 + c16 * 16));
        cp16(sbase + SOFF_BHI + sw, bhp + goff, 16);
        cp16(sbase + SOFF_BLO + sw, blp + goff, 16);
    }
    cp_commit();
}

__global__ void __launch_bounds__(512, 1) gemm_mma() {
    extern __shared__ __align__(1024) char smem[];
    const uint32_t sb = smem_u32(smem);
    const int tid = threadIdx.x;
    const int wid = tid >> 5, lane = tid & 31;

    const int mt = blockIdx.x >> 1;          // 0..2
    const int nt = blockIdx.x & 1;           // 0..1
    const int sp = blockIdx.y;
    const int och0 = mt * 128, z0 = nt * 4;
    const int c0 = (sp * NCHUNK) / NSPL;
    const int c1 = ((sp + 1) * NCHUNK) / NSPL;
    const int n  = c1 - c0;

    const int warp_m = wid >> 2, warp_n = wid & 3;
    const int m0 = warp_m * 32, n0 = warp_n * 64;

    // per-lane ldmatrix addressing
    const int quad = lane >> 3, r8 = lane & 7;
    const int a_row = (quad & 1) * 8 + r8;   // row within 16-row frag
    const int a_sel = quad >> 1;             // k16-half select
    const int b_grp = quad >> 1;             // n-group select (within pair)
    const int b_sel = quad & 1;              // k16-half select
    // base byte offsets (row*128); swizzle applied per-g
    const uint32_t pa0 = (uint32_t)((m0 + a_row) * 128);
    const uint32_t pa1 = (uint32_t)((m0 + 16 + a_row) * 128);
    uint32_t pb[4];
#pragma unroll
    for (int j2 = 0; j2 < 4; j2++)
        pb[j2] = (uint32_t)((n0 + j2 * 16 + b_grp * 8 + r8) * 128);

    float acc[2][8][4];
#pragma unroll
    for (int mi = 0; mi < 2; mi++)
#pragma unroll
        for (int nj = 0; nj < 8; nj++)
#pragma unroll
            for (int e = 0; e < 4; e++) acc[mi][nj][e] = 0.f;

    const uint32_t st[2] = {sb, sb + STAGE_BYTES};

    load_chunk(c0, st[0], tid, och0, z0);
    if (n > 1) load_chunk(c0 + 1, st[1], tid, och0, z0);

    for (int i = 0; i < n; i++) {
        const uint32_t sbase = st[i & 1];
        if (i + 1 < n) cp_wait1(); else cp_wait0();
        __syncthreads();

        // 3 precision passes: (Ahi,Bhi), (Ahi,Blo), (Alo,Bhi)
#pragma unroll
        for (int ps = 0; ps < 3; ps++) {
            const uint32_t Ab = sbase + (ps == 2 ? SOFF_ALO : SOFF_AHI);
            const uint32_t Bb = sbase + (ps == 1 ? SOFF_BLO : SOFF_BHI);
#pragma unroll
            for (int g = 0; g < 4; g++) {
                const uint32_t aoff = (uint32_t)((((g << 1) + a_sel) ^ r8) << 4);
                const uint32_t boff = (uint32_t)((((g << 1) + b_sel) ^ r8) << 4);
                uint32_t a0[4], a1[4];
                ldm4(a0[0], a0[1], a0[2], a0[3], Ab + pa0 + aoff);
                ldm4(a1[0], a1[1], a1[2], a1[3], Ab + pa1 + aoff);
#pragma unroll
                for (int j2 = 0; j2 < 4; j2++) {
                    uint32_t b[4];
                    ldm4(b[0], b[1], b[2], b[3], Bb + pb[j2] + boff);
                    mma16816(acc[0][2 * j2],     a0[0], a0[1], a0[2], a0[3], b[0], b[1]);
                    mma16816(acc[0][2 * j2 + 1], a0[0], a0[1], a0[2], a0[3], b[2], b[3]);
                    mma16816(acc[1][2 * j2],     a1[0], a1[1], a1[2], a1[3], b[0], b[1]);
                    mma16816(acc[1][2 * j2 + 1], a1[0], a1[1], a1[2], a1[3], b[2], b[3]);
                }
            }
        }
        __syncthreads();
        if (i + 2 < n) load_chunk(c0 + i + 2, sbase, tid, och0, z0);
    }

    // epilogue -> g_part[sp][blockIdx.x][128][256]
    float* dst = g_part + (size_t)(sp * 6 + blockIdx.x) * (128 * 256);
    const int gidx = lane >> 2, tid4 = lane & 3;
#pragma unroll
    for (int mi = 0; mi < 2; mi++)
#pragma unroll
        for (int nj = 0; nj < 8; nj++) {
            int row = m0 + 16 * mi + gidx;
            int col = n0 + 8 * nj + tid4 * 2;
            *(float2*)(dst + row * 256 + col) =
                make_float2(acc[mi][nj][0], acc[mi][nj][1]);
            *(float2*)(dst + (row + 8) * 256 + col) =
                make_float2(acc[mi][nj][2], acc[mi][nj][3]);
        }
}

// ---------------------------------------------------------------------------
// Kernel 4: reduce split partials + bias.
// ---------------------------------------------------------------------------
__global__ void reduce_kernel(float* __restrict__ out,
                              const float* __restrict__ bias) {
    int i = blockIdx.x * blockDim.x + threadIdx.x;
    if (i >= NCH * VOX) return;
    int och = i >> 9, v = i & 511;
    int m = och >> 7, ro = och & 127;
    int ntl = v >> 8, rv = v & 255;
    int blk = m * 2 + ntl;
    float s = 0.f;
#pragma unroll
    for (int sp = 0; sp < NSPL; sp++)
        s += g_part[(size_t)(sp * 6 + blk) * (128 * 256) + ro * 256 + rv];
    int d = och >> 4;
    if (d < C0N) s += bias[d];
    out[i] = s;
}

// ---------------------------------------------------------------------------
extern "C" void kernel_launch(void* const* d_in, const int* in_sizes, int n_in,
                              void* d_out, int out_size) {
    const float* x     = (const float*)d_in[0];
    const float* q_in  = (const float*)d_in[1];
    const float* q_out = (const float*)d_in[2];
    const float* w_ss  = (const float*)d_in[3];
    const float* w_vs  = (const float*)d_in[4];
    const float* w_sv  = (const float*)d_in[5];
    const float* w_vv0 = (const float*)d_in[6];
    const float* w_vv1 = (const float*)d_in[7];
    const float* bias  = (const float*)d_in[8];
    float* out = (float*)d_out;

    xpad_kernel<<<(1728 * NCH + 255) / 256, 256>>>(x);

    dim3 bgrid((QN * QN * K3T + 255) / 256, 4);
    build_kern_kernel<<<bgrid, 256>>>(q_in, q_out, w_ss, w_vs, w_sv, w_vv0, w_vv1);

    cudaFuncSetAttribute(gemm_mma, cudaFuncAttributeMaxDynamicSharedMemorySize, SMEM_TOTAL);
    gemm_mma<<<dim3(6, NSPL), 512, SMEM_TOTAL>>>();

    reduce_kernel<<<(NCH * VOX + 255) / 256, 256>>>(out, bias);
}